// round 12
// baseline (speedup 1.0000x reference)
#include <cuda_runtime.h>
#include <cstdint>

// Fixed shapes: B=64, C=3, H=W=256
#define NCAT    5
#define NB      64
#define E_ELEM  196608
#define E4      49152            // float4 positions per sample
#define TPB     128
#define GRID    384              // j-chunks: 384 * 128 = 49152
#define EPSF    1e-6f
#define NPART   15
#define NPAD    16

#define STAGES  6
#define CHUNK   2048             // bytes per array per stage (TPB * 16)
#define TXBYTES (3 * CHUNK)
#define SAMPLE_BYTES ((long long)E_ELEM * 4)

__device__ float g_part[GRID * NPAD];
__device__ int   g_done = 0;     // self-resetting last-block counter

// -------- packed f32x2 helpers ----------------------------------------------
__device__ __forceinline__ unsigned long long f2_add(unsigned long long a, unsigned long long b) {
    unsigned long long r;
    asm("add.rn.f32x2 %0, %1, %2;" : "=l"(r) : "l"(a), "l"(b));
    return r;
}
__device__ __forceinline__ unsigned long long f2_fma(unsigned long long a, unsigned long long b,
                                                     unsigned long long c) {
    unsigned long long r;
    asm("fma.rn.f32x2 %0, %1, %2, %3;" : "=l"(r) : "l"(a), "l"(b), "l"(c));
    return r;
}
__device__ __forceinline__ void f2_unpack(unsigned long long v, float& lo, float& hi) {
    asm("mov.b64 {%0, %1}, %2;" : "=f"(lo), "=f"(hi) : "l"(v));
}

#define NEG1X2 0xBF800000BF800000ULL
#define ABSM2  0x7FFFFFFF7FFFFFFFULL

// -------- smem / mbarrier / bulk-copy helpers --------------------------------
__device__ __forceinline__ uint32_t smem_u32(const void* p) {
    uint32_t a;
    asm("{ .reg .u64 t; cvta.to.shared.u64 t, %1; cvt.u32.u64 %0, t; }" : "=r"(a) : "l"(p));
    return a;
}
__device__ __forceinline__ void mbar_init(uint32_t mbar, uint32_t count) {
    asm volatile("mbarrier.init.shared.b64 [%0], %1;" :: "r"(mbar), "r"(count) : "memory");
}
__device__ __forceinline__ void mbar_expect_tx(uint32_t mbar, uint32_t bytes) {
    asm volatile("mbarrier.arrive.expect_tx.shared.b64 _, [%0], %1;"
                 :: "r"(mbar), "r"(bytes) : "memory");
}
__device__ __forceinline__ void mbar_wait(uint32_t mbar, uint32_t parity) {
    asm volatile(
        "{\n\t.reg .pred P;\n\t"
        "W%=:\n\t"
        "mbarrier.try_wait.parity.acquire.cta.shared::cta.b64 P, [%0], %1;\n\t"
        "@!P bra W%=;\n\t}"
        :: "r"(mbar), "r"(parity) : "memory");
}
__device__ __forceinline__ void bulk_cp(uint32_t dst_smem, const void* src, uint32_t mbar) {
    asm volatile(
        "cp.async.bulk.shared::cta.global.mbarrier::complete_tx::bytes [%0], [%1], %2, [%3];"
        :: "r"(dst_smem), "l"(src), "r"((uint32_t)CHUNK), "r"(mbar) : "memory");
}

// ---------------------------------------------------------------------------
// Uniform blocks: block = j-chunk of 128 float4 positions; 64 pipeline
// iterations over ALL samples in cat-sorted order. TMA streams never stall at
// category boundaries; consumers flush register accumulators per segment.
// ---------------------------------------------------------------------------
__global__ void __launch_bounds__(TPB)
k_fused(const float* __restrict__ restored,
        const float* __restrict__ clean,
        const int*   __restrict__ de_id,
        const float* __restrict__ un,
        float*       __restrict__ out) {
    __shared__ int   s_id[NB];
    __shared__ int   s_idx[NB];          // sample indices, cat-sorted
    __shared__ int   s_start[NCAT + 1];
    __shared__ int   s_cnt[NCAT];
    __shared__ float s_invc[NCAT];
    __shared__ float swarp[NPART][4];
    __shared__ int   s_last;
    __shared__ __align__(128) unsigned char s_data[STAGES][3][CHUNK];  // 36KB
    __shared__ __align__(8)  unsigned long long s_full[STAGES];
    __shared__ float sred[NPART][TPB];   // finalize scratch

    const int tid = threadIdx.x;

    // ---- setup: ids, mbar init ----
    if (tid < NB) {
        int c = de_id[tid];
        s_id[tid] = c < 0 ? 0 : (c >= NCAT ? NCAT - 1 : c);
    }
    if (tid == TPB - 1) {
#pragma unroll
        for (int s = 0; s < STAGES; ++s) mbar_init(smem_u32(&s_full[s]), 1);
    }
    __syncthreads();
    // rank-sort all 64 samples by (cat, index)
    if (tid < NB) {
        const int myc = s_id[tid];
        int rank = 0;
#pragma unroll
        for (int b = 0; b < NB; ++b) {
            int cb = s_id[b];
            rank += (cb < myc) || (cb == myc && b < tid);
        }
        s_idx[rank] = tid;
    } else if (tid < NB + NCAT) {
        int c = tid - NB, cnt = 0;
#pragma unroll
        for (int b = 0; b < NB; ++b) cnt += (s_id[b] == c);
        s_cnt[c]  = cnt;
        s_invc[c] = 1.0f / (float)(cnt > 0 ? cnt : 1);
    } else if (tid < NB + NCAT + NCAT + 1) {
        int c = tid - NB - NCAT, st = 0;
#pragma unroll
        for (int b = 0; b < NB; ++b) st += (s_id[b] < c);
        s_start[c] = st;
    }
    __syncthreads();

    const long long jbyte = (long long)blockIdx.x * (TPB * 16);
    const char* __restrict__ bu = (const char*)un;
    const char* __restrict__ br = (const char*)restored;
    const char* __restrict__ bc = (const char*)clean;

    // ---- pipeline prologue: first STAGES samples ----
    if (tid == 0) {
#pragma unroll
        for (int p = 0; p < STAGES; ++p) {
            long long so = (long long)s_idx[p] * SAMPLE_BYTES + jbyte;
            uint32_t mb = smem_u32(&s_full[p]);
            mbar_expect_tx(mb, TXBYTES);
            bulk_cp(smem_u32(&s_data[p][0][0]), bu + so, mb);
            bulk_cp(smem_u32(&s_data[p][1][0]), br + so, mb);
            bulk_cp(smem_u32(&s_data[p][2][0]), bc + so, mb);
        }
    }

    // ---- main loop: 64 uniform iterations, flush at category boundaries ----
    float vals[NPART];
    int stage = 0, phase = 0;
    const int toff = tid * 16;
#pragma unroll
    for (int c = 0; c < NCAT; ++c) {
        unsigned long long U0 = 0ull, U1 = 0ull;
        unsigned long long A0 = 0ull, A1 = 0ull;
        const int ke = s_start[c + 1];
        for (int k = s_start[c]; k < ke; ++k) {
            mbar_wait(smem_u32(&s_full[stage]), phase);

            ulonglong2 u  = *(const ulonglong2*)&s_data[stage][0][toff];
            ulonglong2 r  = *(const ulonglong2*)&s_data[stage][1][toff];
            ulonglong2 cl = *(const ulonglong2*)&s_data[stage][2][toff];
            U0 = f2_add(U0, u.x);
            U1 = f2_add(U1, u.y);
            A0 = f2_add(A0, f2_fma(r.x, NEG1X2, cl.x) & ABSM2);
            A1 = f2_add(A1, f2_fma(r.y, NEG1X2, cl.y) & ABSM2);

            __syncthreads();             // all consumed -> stage free
            if (tid == 0 && k + STAGES < NB) {
                long long so = (long long)s_idx[k + STAGES] * SAMPLE_BYTES + jbyte;
                uint32_t mb = smem_u32(&s_full[stage]);
                mbar_expect_tx(mb, TXBYTES);
                bulk_cp(smem_u32(&s_data[stage][0][0]), bu + so, mb);
                bulk_cp(smem_u32(&s_data[stage][1][0]), br + so, mb);
                bulk_cp(smem_u32(&s_data[stage][2][0]), bc + so, mb);
            }
            if (++stage == STAGES) { stage = 0; phase ^= 1; }
        }
        // flush this category (registers only; no sync, stream keeps flowing)
        float u0, u1, u2, u3, a0, a1, a2, a3;
        f2_unpack(U0, u0, u1);  f2_unpack(U1, u2, u3);
        f2_unpack(A0, a0, a1);  f2_unpack(A1, a2, a3);
        const float ic = s_invc[c];
        float s0 = 1.0f / (u0 * ic + EPSF);
        float s1 = 1.0f / (u1 * ic + EPSF);
        float s2 = 1.0f / (u2 * ic + EPSF);
        float s3 = 1.0f / (u3 * ic + EPSF);
        vals[c]      = fmaf(a3, s3, fmaf(a2, s2, fmaf(a1, s1, a0 * s0)));
        vals[5 + c]  = (a0 + a1) + (a2 + a3);
        vals[10 + c] = (u0 + u1) + (u2 + u3);
    }

    // ---- block reduce: warp shuffle then 4-warp combine ----
#pragma unroll
    for (int v = 0; v < NPART; ++v) {
#pragma unroll
        for (int o = 16; o > 0; o >>= 1)
            vals[v] += __shfl_xor_sync(0xffffffffu, vals[v], o);
    }
    if ((tid & 31) == 0) {
        int w = tid >> 5;
#pragma unroll
        for (int v = 0; v < NPART; ++v) swarp[v][w] = vals[v];
    }
    __syncthreads();
    if (tid < NPART)
        g_part[blockIdx.x * NPAD + tid] =
            swarp[tid][0] + swarp[tid][1] + swarp[tid][2] + swarp[tid][3];

    // ---- last-block finalize (deterministic fixed-order reads) ----
    __threadfence();
    __syncthreads();
    if (tid == 0) s_last = (atomicAdd(&g_done, 1) == GRID - 1);
    __syncthreads();
    if (!s_last) return;
    __threadfence();

    {
        // 384 rows / 128 threads = 3 rows each (NPAD=16 floats = 4 float4)
        float acc[NPART];
#pragma unroll
        for (int v = 0; v < NPART; ++v) acc[v] = 0.0f;
        const float4* gp4 = reinterpret_cast<const float4*>(g_part);
        int base = tid * 3 * (NPAD / 4);
#pragma unroll
        for (int r = 0; r < 3; ++r) {
            float4 q0 = __ldcg(gp4 + base + 0);
            float4 q1 = __ldcg(gp4 + base + 1);
            float4 q2 = __ldcg(gp4 + base + 2);
            float4 q3 = __ldcg(gp4 + base + 3);
            base += NPAD / 4;
            acc[0] += q0.x;  acc[1] += q0.y;  acc[2]  += q0.z;  acc[3]  += q0.w;
            acc[4] += q1.x;  acc[5] += q1.y;  acc[6]  += q1.z;  acc[7]  += q1.w;
            acc[8] += q2.x;  acc[9] += q2.y;  acc[10] += q2.z;  acc[11] += q2.w;
            acc[12] += q3.x; acc[13] += q3.y; acc[14] += q3.z;
        }
#pragma unroll
        for (int v = 0; v < NPART; ++v) sred[v][tid] = acc[v];
        __syncthreads();
#pragma unroll
        for (int st = TPB / 2; st > 0; st >>= 1) {
            if (tid < st) {
#pragma unroll
                for (int v = 0; v < NPART; ++v) sred[v][tid] += sred[v][tid + st];
            }
            __syncthreads();
        }
        if (tid == 0) {
            const float Ef = (float)E_ELEM;
            float totalsum = 0.0f, cum_sc = 0.0f, cumN = 0.0f;
            int num_ne = 0;
#pragma unroll
            for (int c = 0; c < NCAT; ++c) if (s_cnt[c] > 0) num_ne++;
#pragma unroll
            for (int c = 0; c < NCAT; ++c) {
                int   cnt  = s_cnt[c];
                bool  ne   = cnt > 0;
                float safe = (float)(cnt > 0 ? cnt : 1);
                float S_sc = sred[c][0];
                float S_ab = sred[5 + c][0];
                float S_un = sred[10 + c][0];

                cum_sc += S_sc;
                cumN   += (float)cnt * Ef;
                float cum_l1 = cum_sc / fmaxf(cumN, 1.0f);
                float un_num = S_un / (safe * Ef) + EPSF;
                float bn     = ne ? 2.0f * logf(un_num) : 0.0f;
                float unc    = ne ? cum_l1 : 0.0f;
                float old_l  = ne ? S_ab / (safe * Ef) : 0.0f;
                float cat_l  = unc + bn;
                totalsum += cat_l;

                out[1 + c]  = cat_l;
                out[6 + c]  = old_l;
                out[11 + c] = bn;
                out[16 + c] = unc;
            }
            out[0] = totalsum / (float)(num_ne > 0 ? num_ne : 1);
            g_done = 0;   // self-reset for graph replay
        }
    }
}

// ---------------------------------------------------------------------------
extern "C" void kernel_launch(void* const* d_in, const int* in_sizes, int n_in,
                              void* d_out, int out_size) {
    const float* restored = (const float*)d_in[0];
    const float* clean    = (const float*)d_in[1];
    const int*   de_id    = (const int*)d_in[2];
    const float* un       = (const float*)d_in[3];
    float*       out      = (float*)d_out;

    k_fused<<<GRID, TPB>>>(restored, clean, de_id, un, out);
}

// round 13
// speedup vs baseline: 1.0145x; 1.0145x over previous
#include <cuda_runtime.h>
#include <cstdint>

// Fixed shapes: B=64, C=3, H=W=256
#define NCAT    5
#define NB      64
#define E_ELEM  196608
#define E4      49152            // float4 positions per sample
#define TPB     256
#define JBLK    192              // j-chunks: 192 * 256 = 49152
#define GRID    (NCAT * JBLK)    // 960 blocks, single wave
#define EPSF    1e-6f

#define STAGES  3
#define CHUNK   4096             // bytes per array per stage (TPB * 16)
#define TXBYTES (3 * CHUNK)

__device__ float4 g_part[GRID];  // cat-major: [cat][jc] -> (scaled, abs, un, 0)
__device__ int    g_done = 0;    // self-resetting last-block counter

// -------- packed f32x2 helpers ----------------------------------------------
__device__ __forceinline__ unsigned long long f2_add(unsigned long long a, unsigned long long b) {
    unsigned long long r;
    asm("add.rn.f32x2 %0, %1, %2;" : "=l"(r) : "l"(a), "l"(b));
    return r;
}
__device__ __forceinline__ unsigned long long f2_fma(unsigned long long a, unsigned long long b,
                                                     unsigned long long c) {
    unsigned long long r;
    asm("fma.rn.f32x2 %0, %1, %2, %3;" : "=l"(r) : "l"(a), "l"(b), "l"(c));
    return r;
}
__device__ __forceinline__ void f2_unpack(unsigned long long v, float& lo, float& hi) {
    asm("mov.b64 {%0, %1}, %2;" : "=f"(lo), "=f"(hi) : "l"(v));
}

#define NEG1X2 0xBF800000BF800000ULL
#define ABSM2  0x7FFFFFFF7FFFFFFFULL

// -------- smem / mbarrier / bulk-copy helpers --------------------------------
__device__ __forceinline__ uint32_t smem_u32(const void* p) {
    uint32_t a;
    asm("{ .reg .u64 t; cvta.to.shared.u64 t, %1; cvt.u32.u64 %0, t; }" : "=r"(a) : "l"(p));
    return a;
}
__device__ __forceinline__ void mbar_init(uint32_t mbar, uint32_t count) {
    asm volatile("mbarrier.init.shared.b64 [%0], %1;" :: "r"(mbar), "r"(count) : "memory");
}
__device__ __forceinline__ void mbar_expect_tx(uint32_t mbar, uint32_t bytes) {
    asm volatile("mbarrier.arrive.expect_tx.shared.b64 _, [%0], %1;"
                 :: "r"(mbar), "r"(bytes) : "memory");
}
__device__ __forceinline__ void mbar_arrive(uint32_t mbar) {
    asm volatile("mbarrier.arrive.release.cta.shared::cta.b64 _, [%0];"
                 :: "r"(mbar) : "memory");
}
__device__ __forceinline__ void mbar_wait(uint32_t mbar, uint32_t parity) {
    asm volatile(
        "{\n\t.reg .pred P;\n\t"
        "W%=:\n\t"
        "mbarrier.try_wait.parity.acquire.cta.shared::cta.b64 P, [%0], %1;\n\t"
        "@!P bra W%=;\n\t}"
        :: "r"(mbar), "r"(parity) : "memory");
}
__device__ __forceinline__ void bulk_cp(uint32_t dst_smem, const void* src, uint32_t mbar) {
    asm volatile(
        "cp.async.bulk.shared::cta.global.mbarrier::complete_tx::bytes [%0], [%1], %2, [%3];"
        :: "r"(dst_smem), "l"(src), "r"((uint32_t)CHUNK), "r"(mbar) : "memory");
}

// ---------------------------------------------------------------------------
// Block = (cat = bid % 5, j-chunk = bid / 5). TMA pipeline with full/empty
// mbarriers: consumers never hit a block-wide barrier; warps skew up to
// STAGES deep. tid0 (producer) waits for a stage's 8 warp-arrivals before
// reissuing into it.
// ---------------------------------------------------------------------------
__global__ void __launch_bounds__(TPB)
k_fused(const float* __restrict__ restored,
        const float* __restrict__ clean,
        const int*   __restrict__ de_id,
        const float* __restrict__ un,
        float*       __restrict__ out) {
    __shared__ int   s_id[NB];
    __shared__ int   s_off[NB];         // this category's sample offsets (b*E4)
    __shared__ int   s_cnt[NCAT];
    __shared__ int   s_n;
    __shared__ float s_ic;
    __shared__ float swarp[3][8];
    __shared__ int   s_last;
    __shared__ __align__(128) unsigned char s_data[STAGES][3][CHUNK];  // 36KB
    __shared__ __align__(8)  unsigned long long s_full[STAGES];
    __shared__ __align__(8)  unsigned long long s_empty[STAGES];

    const int tid = threadIdx.x;
    const int c   = blockIdx.x % NCAT;
    const int jc  = blockIdx.x / NCAT;

    // ---- parallel setup: ids, barrier init, rank-scatter, counts ----
    if (tid < NB) {
        int cc = de_id[tid];
        s_id[tid] = cc < 0 ? 0 : (cc >= NCAT ? NCAT - 1 : cc);
    }
    if (tid == TPB - 1) {
#pragma unroll
        for (int s = 0; s < STAGES; ++s) {
            mbar_init(smem_u32(&s_full[s]), 1);
            mbar_init(smem_u32(&s_empty[s]), TPB / 32);   // one arrive per warp
        }
    }
    __syncthreads();
    if (tid < NB) {
        if (s_id[tid] == c) {
            int rank = 0;
#pragma unroll
            for (int b = 0; b < NB; ++b) rank += (b < tid) && (s_id[b] == c);
            s_off[rank] = tid * E4;
        }
    } else if (tid < NB + NCAT) {       // counts on 5 threads
        int cc = tid - NB, cnt = 0;
#pragma unroll
        for (int b = 0; b < NB; ++b) cnt += (s_id[b] == cc);
        s_cnt[cc] = cnt;
        if (cc == c) {
            s_n  = cnt;
            s_ic = 1.0f / (float)(cnt > 0 ? cnt : 1);
        }
    }
    __syncthreads();

    const int n = s_n;
    const long long jbyte = (long long)(jc * TPB) * 16;   // byte offset of this j-chunk
    const char* __restrict__ bu = (const char*)un;
    const char* __restrict__ br = (const char*)restored;
    const char* __restrict__ bc = (const char*)clean;

    // ---- pipeline prologue: issue first min(STAGES, n) samples ----
    if (tid == 0) {
        int ni = n < STAGES ? n : STAGES;
        for (int p = 0; p < ni; ++p) {
            long long so = (long long)s_off[p] * 16 + jbyte;
            uint32_t mb = smem_u32(&s_full[p]);
            mbar_expect_tx(mb, TXBYTES);
            bulk_cp(smem_u32(&s_data[p][0][0]), bu + so, mb);
            bulk_cp(smem_u32(&s_data[p][1][0]), br + so, mb);
            bulk_cp(smem_u32(&s_data[p][2][0]), bc + so, mb);
        }
    }

    // ---- main loop: no block-wide barrier; warps skew across stages ----
    unsigned long long U0 = 0ull, U1 = 0ull;
    unsigned long long A0 = 0ull, A1 = 0ull;
    int stage = 0, phase = 0;
    const int toff = tid * 16;
    const bool lane0 = (tid & 31) == 0;
    for (int k = 0; k < n; ++k) {
        mbar_wait(smem_u32(&s_full[stage]), phase);

        ulonglong2 u  = *(const ulonglong2*)&s_data[stage][0][toff];
        ulonglong2 r  = *(const ulonglong2*)&s_data[stage][1][toff];
        ulonglong2 cl = *(const ulonglong2*)&s_data[stage][2][toff];
        U0 = f2_add(U0, u.x);
        U1 = f2_add(U1, u.y);
        A0 = f2_add(A0, f2_fma(r.x, NEG1X2, cl.x) & ABSM2);
        A1 = f2_add(A1, f2_fma(r.y, NEG1X2, cl.y) & ABSM2);

        // accumulators consumed the loads (register dataflow) -> warp done
        __syncwarp();
        if (lane0) mbar_arrive(smem_u32(&s_empty[stage]));

        if (tid == 0 && k + STAGES < n) {
            // wait for all 8 warps to drain this stage, then reissue
            mbar_wait(smem_u32(&s_empty[stage]), phase);
            long long so = (long long)s_off[k + STAGES] * 16 + jbyte;
            uint32_t mb = smem_u32(&s_full[stage]);
            mbar_expect_tx(mb, TXBYTES);
            bulk_cp(smem_u32(&s_data[stage][0][0]), bu + so, mb);
            bulk_cp(smem_u32(&s_data[stage][1][0]), br + so, mb);
            bulk_cp(smem_u32(&s_data[stage][2][0]), bc + so, mb);
        }
        if (++stage == STAGES) { stage = 0; phase ^= 1; }
    }

    // ---- flush: scale and dot ----
    float u0, u1, u2, u3, a0, a1, a2, a3;
    f2_unpack(U0, u0, u1);  f2_unpack(U1, u2, u3);
    f2_unpack(A0, a0, a1);  f2_unpack(A1, a2, a3);
    const float ic = s_ic;
    float s0 = 1.0f / (u0 * ic + EPSF);
    float s1 = 1.0f / (u1 * ic + EPSF);
    float s2 = 1.0f / (u2 * ic + EPSF);
    float s3 = 1.0f / (u3 * ic + EPSF);

    float vsc = fmaf(a3, s3, fmaf(a2, s2, fmaf(a1, s1, a0 * s0)));  // scaled
    float vab = (a0 + a1) + (a2 + a3);                               // abs
    float vun = (u0 + u1) + (u2 + u3);                               // un total

    // ---- warp-shuffle reduce, then 8-warp combine ----
#pragma unroll
    for (int o = 16; o > 0; o >>= 1) {
        vsc += __shfl_xor_sync(0xffffffffu, vsc, o);
        vab += __shfl_xor_sync(0xffffffffu, vab, o);
        vun += __shfl_xor_sync(0xffffffffu, vun, o);
    }
    if (lane0) {
        int w = tid >> 5;
        swarp[0][w] = vsc; swarp[1][w] = vab; swarp[2][w] = vun;
    }
    __syncthreads();
    if (tid == 0) {
        float S = 0.0f, A = 0.0f, Uu = 0.0f;
#pragma unroll
        for (int w = 0; w < 8; ++w) { S += swarp[0][w]; A += swarp[1][w]; Uu += swarp[2][w]; }
        float4 q; q.x = S; q.y = A; q.z = Uu; q.w = 0.0f;
        g_part[c * JBLK + jc] = q;     // cat-major layout
    }

    // ---- last-block finalize (deterministic fixed-order reads) ----
    __threadfence();
    __syncthreads();
    if (tid == 0) s_last = (atomicAdd(&g_done, 1) == GRID - 1);
    __syncthreads();
    if (!s_last) return;
    __threadfence();

    __shared__ float f_sc[NCAT][48], f_ab[NCAT][48], f_un[NCAT][48];
    if (tid < NCAT * 48) {                 // 240 threads
        int cc = tid / 48, g = tid % 48;
        float sc = 0.0f, ab = 0.0f, uu = 0.0f;
#pragma unroll
        for (int r = 0; r < 4; ++r) {
            float4 q = __ldcg(&g_part[cc * JBLK + g * 4 + r]);
            sc += q.x; ab += q.y; uu += q.z;
        }
        f_sc[cc][g] = sc; f_ab[cc][g] = ab; f_un[cc][g] = uu;
    }
    __syncthreads();
    __shared__ float stot[3][NCAT];
    if (tid < NCAT) {
        float sc = 0.0f, ab = 0.0f, uu = 0.0f;
#pragma unroll
        for (int g = 0; g < 48; ++g) { sc += f_sc[tid][g]; ab += f_ab[tid][g]; uu += f_un[tid][g]; }
        stot[0][tid] = sc; stot[1][tid] = ab; stot[2][tid] = uu;
    }
    __syncthreads();

    if (tid == 0) {
        const float Ef = (float)E_ELEM;
        float totalsum = 0.0f, cum_sc = 0.0f, cumN = 0.0f;
        int num_ne = 0;
#pragma unroll
        for (int cc = 0; cc < NCAT; ++cc) if (s_cnt[cc] > 0) num_ne++;
#pragma unroll
        for (int cc = 0; cc < NCAT; ++cc) {
            int   cnt  = s_cnt[cc];
            bool  ne   = cnt > 0;
            float safe = (float)(cnt > 0 ? cnt : 1);
            float S_sc = stot[0][cc];
            float S_ab = stot[1][cc];
            float S_un = stot[2][cc];

            cum_sc += S_sc;
            cumN   += (float)cnt * Ef;
            float cum_l1 = cum_sc / fmaxf(cumN, 1.0f);
            float un_num = S_un / (safe * Ef) + EPSF;
            float bn     = ne ? 2.0f * logf(un_num) : 0.0f;
            float unc    = ne ? cum_l1 : 0.0f;
            float old_l  = ne ? S_ab / (safe * Ef) : 0.0f;
            float cat_l  = unc + bn;
            totalsum += cat_l;

            out[1 + cc]  = cat_l;
            out[6 + cc]  = old_l;
            out[11 + cc] = bn;
            out[16 + cc] = unc;
        }
        out[0] = totalsum / (float)(num_ne > 0 ? num_ne : 1);
        g_done = 0;   // self-reset for graph replay
    }
}

// ---------------------------------------------------------------------------
extern "C" void kernel_launch(void* const* d_in, const int* in_sizes, int n_in,
                              void* d_out, int out_size) {
    const float* restored = (const float*)d_in[0];
    const float* clean    = (const float*)d_in[1];
    const int*   de_id    = (const int*)d_in[2];
    const float* un       = (const float*)d_in[3];
    float*       out      = (float*)d_out;

    k_fused<<<GRID, TPB>>>(restored, clean, de_id, un, out);
}